// round 3
// baseline (speedup 1.0000x reference)
#include <cuda_runtime.h>
#include <math.h>

#define L_    256
#define B_    64
#define D_    1024
#define H_    512
#define R_    8
#define C_    6
#define WIN_  10
#define N_    (B_*L_)
#define DH_   (D_+H_)
#define EPB   5266   // edges per batch (banded window pattern)

// ---------------- scratch (allocation-free: __device__ globals) ----------------
__device__ float g_scale [(size_t)N_*L_];     // [ (s*B+b), i ]  16 MB
__device__ float g_edge  [(size_t)B_*EPB];    // edge_norm        1.35 MB
__device__ float g_em    [(size_t)N_*DH_];    // [n, x|h2]        96 MB
__device__ float g_hall  [(size_t)N_*R_*H_];  // [n, r, h]        256 MB
__device__ float g_h1    [(size_t)N_*H_];
__device__ float g_nbr   [(size_t)N_*H_];
__device__ float g_xt    [(size_t)N_*DH_];
__device__ float g_G     [(size_t)B_*L_*L_];  // attention logits/probs
__device__ float g_att   [(size_t)N_*DH_];
__device__ float g_hid   [(size_t)N_*H_];

// edges with anchor j < i  (edges(j) = min(255,j+10)-max(0,j-10)+1)
__device__ __forceinline__ int edge_prefix(int i) {
    if (i <= 10)  return i*11 + (i*(i-1))/2;
    if (i <= 246) return 155 + (i-10)*21;
    int t = i - 246;
    return 5111 + 20*t - (t*(t-1))/2;
}

// ---------------- em[:, 0:D] = x  (node-major transpose of features) ----------------
__global__ void k_embed_x(const float* __restrict__ f) {
    int j = blockIdx.x, b = blockIdx.y;
    const float4* src = reinterpret_cast<const float4*>(f + ((size_t)j*B_ + b)*D_);
    float4* dst = reinterpret_cast<float4*>(g_em + ((size_t)b*L_ + j)*DH_);
    dst[threadIdx.x] = src[threadIdx.x];   // 256 threads * float4 = 1024 floats
}

// ---------------- edge_norm: windowed renormalized softmax ----------------
// alpha[b,i,k] = exp(scale[k,b,i]) / Z ; edge_norm = exp(v_k) / (S_win + 1e-10*(S_all-S_win))
__global__ void k_edge() {
    int b = blockIdx.x;
    int i = threadIdx.x;                 // anchor
    int ks = max(0, i - WIN_), ke = min(L_-1, i + WIN_);
    float wv[2*WIN_ + 1];
    float m = -1e30f, S = 0.f;
    for (int s = 0; s < L_; s++) {
        float v = __ldg(g_scale + ((size_t)s*B_ + b)*L_ + i);
        float mn = fmaxf(m, v);
        S = S*__expf(m - mn) + __expf(v - mn);
        m = mn;
        if (s >= ks && s <= ke) wv[s - ks] = v;
    }
    int cnt = ke - ks + 1;
    float Sw = 0.f;
    for (int t = 0; t < cnt; t++) { wv[t] = __expf(wv[t] - m); Sw += wv[t]; }
    float inv = 1.f / (Sw + 1e-10f*(S - Sw));
    float* out = g_edge + (size_t)b*EPB + edge_prefix(i);
    for (int t = 0; t < cnt; t++) out[t] = wv[t]*inv;
}

// ---------------- RGCN aggregation: h1[dst] += sum_e w_e * h_all[src, rel] ----------------
__global__ void k_rgcn_agg(const int* __restrict__ sp) {
    int n = blockIdx.x;
    int b = n / L_, k = n % L_;          // dst = (b, k)
    int spk = __ldg(sp + k*B_ + b);
    int t = threadIdx.x;                  // 256 threads, 2 h each
    float a0 = 0.f, a1 = 0.f;
    int is = max(0, k - WIN_), ie = min(L_-1, k + WIN_);
    for (int i = is; i <= ie; i++) {
        float w = __ldg(g_edge + (size_t)b*EPB + edge_prefix(i) + (k - max(0, i - WIN_)));
        int spi = __ldg(sp + i*B_ + b);
        int r = spi*4 + spk*2 + ((i < k) ? 0 : 1);
        const float* row = g_hall + (((size_t)(b*L_ + i))*R_ + r)*H_;
        a0 += w*__ldg(row + t);
        a1 += w*__ldg(row + t + 256);
    }
    g_h1[(size_t)n*H_ + t]       += a0;
    g_h1[(size_t)n*H_ + t + 256] += a1;
}

// ---------------- GraphConv neighbor sum: nbr[dst] = sum_e h1[src] ----------------
__global__ void k_nbr_agg() {
    int n = blockIdx.x;
    int b = n / L_, k = n % L_;
    int t = threadIdx.x;
    float a0 = 0.f, a1 = 0.f;
    int is = max(0, k - WIN_), ie = min(L_-1, k + WIN_);
    for (int i = is; i <= ie; i++) {
        const float* row = g_h1 + (size_t)(b*L_ + i)*H_;
        a0 += __ldg(row + t);
        a1 += __ldg(row + t + 256);
    }
    g_nbr[(size_t)n*H_ + t]       = a0;
    g_nbr[(size_t)n*H_ + t + 256] = a1;
}

// ---------------- generic fp32 tiled GEMM (64x64x16, 4x4 microtile, batched) ----------------
// C = A(MxK) * B(KxN)   (TRANSB: B stored as (N,K) row-major)
template<int TRANSB>
__global__ void __launch_bounds__(256)
k_gemm(const float* __restrict__ A, const float* __restrict__ Bm,
       const float* __restrict__ bias, float* __restrict__ Cm,
       int M, int N, int K, int lda, int ldb, int ldc,
       long sA, long sB, long sC, int epi, int accum)
{
    __shared__ float As[16][64];
    __shared__ float Bs[16][64];
    int z = blockIdx.z;
    A  += (size_t)z * sA;
    Bm += (size_t)z * sB;
    Cm += (size_t)z * sC;
    int m0 = blockIdx.y * 64, n0 = blockIdx.x * 64;
    int tid = threadIdx.x;
    int tx = tid & 15, ty = tid >> 4;

    int am = tid >> 2, ak = (tid & 3) * 4;      // A tile load
    int bk = tid >> 4, bn = (tid & 15) * 4;     // B NN load
    int bn2 = tid >> 2, bk2 = (tid & 3) * 4;    // B NT load

    float acc[4][4];
#pragma unroll
    for (int i = 0; i < 4; i++)
#pragma unroll
        for (int j = 0; j < 4; j++) acc[i][j] = 0.f;

    for (int k0 = 0; k0 < K; k0 += 16) {
        float4 av = *reinterpret_cast<const float4*>(A + (size_t)(m0 + am)*lda + k0 + ak);
        As[ak+0][am] = av.x; As[ak+1][am] = av.y; As[ak+2][am] = av.z; As[ak+3][am] = av.w;
        if (TRANSB == 0) {
            float4 bv = *reinterpret_cast<const float4*>(Bm + (size_t)(k0 + bk)*ldb + n0 + bn);
            *reinterpret_cast<float4*>(&Bs[bk][bn]) = bv;
        } else {
            float4 bv = *reinterpret_cast<const float4*>(Bm + (size_t)(n0 + bn2)*ldb + k0 + bk2);
            Bs[bk2+0][bn2] = bv.x; Bs[bk2+1][bn2] = bv.y; Bs[bk2+2][bn2] = bv.z; Bs[bk2+3][bn2] = bv.w;
        }
        __syncthreads();
#pragma unroll
        for (int kk = 0; kk < 16; kk++) {
            float4 a  = *reinterpret_cast<const float4*>(&As[kk][ty*4]);
            float4 bb = *reinterpret_cast<const float4*>(&Bs[kk][tx*4]);
            acc[0][0] += a.x*bb.x; acc[0][1] += a.x*bb.y; acc[0][2] += a.x*bb.z; acc[0][3] += a.x*bb.w;
            acc[1][0] += a.y*bb.x; acc[1][1] += a.y*bb.y; acc[1][2] += a.y*bb.z; acc[1][3] += a.y*bb.w;
            acc[2][0] += a.z*bb.x; acc[2][1] += a.z*bb.y; acc[2][2] += a.z*bb.z; acc[2][3] += a.z*bb.w;
            acc[3][0] += a.w*bb.x; acc[3][1] += a.w*bb.y; acc[3][2] += a.w*bb.z; acc[3][3] += a.w*bb.w;
        }
        __syncthreads();
    }
#pragma unroll
    for (int i = 0; i < 4; i++) {
        int row = m0 + ty*4 + i;
#pragma unroll
        for (int j = 0; j < 4; j++) {
            int col = n0 + tx*4 + j;
            float v = acc[i][j];
            float* p = Cm + (size_t)row*ldc + col;
            if (accum) v += *p;
            if (bias)  v += __ldg(bias + col);
            if (epi == 1) v = fmaxf(v, 0.f);
            else if (epi == 2) v = tanhf(v);
            *p = v;
        }
    }
}

// ---------------- row softmax over G (256 cols) ----------------
__global__ void k_softmax_g() {
    int row = blockIdx.x;                 // b*L + t
    float* p = g_G + (size_t)row*L_;
    int t = threadIdx.x;
    __shared__ float red[256];
    float v = p[t];
    red[t] = v; __syncthreads();
    for (int s = 128; s > 0; s >>= 1) { if (t < s) red[t] = fmaxf(red[t], red[t+s]); __syncthreads(); }
    float m = red[0]; __syncthreads();
    float e = __expf(v - m);
    red[t] = e; __syncthreads();
    for (int s = 128; s > 0; s >>= 1) { if (t < s) red[t] += red[t+s]; __syncthreads(); }
    p[t] = e / red[0];
}

// ---------------- fc + log_softmax (warp per node) ----------------
__global__ void k_fc(const float* __restrict__ Wfc, const float* __restrict__ bfc,
                     float* __restrict__ out) {
    int warp = (blockIdx.x * blockDim.x + threadIdx.x) >> 5;
    int lane = threadIdx.x & 31;
    if (warp >= N_) return;
    const float* h = g_hid + (size_t)warp*H_;
    float acc[6] = {0,0,0,0,0,0};
    for (int k = lane; k < H_; k += 32) {
        float hv = __ldg(h + k);
        const float* w = Wfc + k*C_;
#pragma unroll
        for (int c = 0; c < C_; c++) acc[c] += hv * __ldg(w + c);
    }
#pragma unroll
    for (int c = 0; c < C_; c++)
#pragma unroll
        for (int o = 16; o > 0; o >>= 1) acc[c] += __shfl_xor_sync(0xffffffffu, acc[c], o);
    if (lane == 0) {
        float z[6], m = -1e30f;
#pragma unroll
        for (int c = 0; c < C_; c++) { z[c] = acc[c] + __ldg(bfc + c); m = fmaxf(m, z[c]); }
        float s = 0.f;
#pragma unroll
        for (int c = 0; c < C_; c++) s += expf(z[c] - m);
        float lse = logf(s);
#pragma unroll
        for (int c = 0; c < C_; c++) out[(size_t)warp*C_ + c] = z[c] - m - lse;
    }
}

// ---------------- host ----------------
static float* sym_addr(const void* symbol) {
    void* p = nullptr;
    cudaGetSymbolAddress(&p, symbol);
    return (float*)p;
}

extern "C" void kernel_launch(void* const* d_in, const int* in_sizes, int n_in,
                              void* d_out, int out_size) {
    const float* features = (const float*)d_in[0];
    const float* Wscalar  = (const float*)d_in[1];
    const float* W_rel    = (const float*)d_in[2];
    const float* W_root   = (const float*)d_in[3];
    const float* b_rgcn   = (const float*)d_in[4];
    const float* W_nbr    = (const float*)d_in[5];
    const float* W_self   = (const float*)d_in[6];
    const float* b_gc     = (const float*)d_in[7];
    const float* W_match  = (const float*)d_in[8];
    const float* b_match  = (const float*)d_in[9];
    const float* W_lin    = (const float*)d_in[10];
    const float* b_lin    = (const float*)d_in[11];
    const float* W_fc     = (const float*)d_in[12];
    const float* b_fc     = (const float*)d_in[13];
    const int*   speakers = (const int*)d_in[14];
    float* out = (float*)d_out;

    float* p_scale = sym_addr(g_scale);
    float* p_em    = sym_addr(g_em);
    float* p_hall  = sym_addr(g_hall);
    float* p_h1    = sym_addr(g_h1);
    float* p_nbr   = sym_addr(g_nbr);
    float* p_xt    = sym_addr(g_xt);
    float* p_G     = sym_addr(g_G);
    float* p_att   = sym_addr(g_att);
    float* p_hid   = sym_addr(g_hid);

    // 1. em[:, 0:D] = x (node-major features)
    k_embed_x<<<dim3(L_, B_), 256>>>(features);

    // 2. scale = features_flat(16384x1024) @ Wscalar(1024x256)
    k_gemm<0><<<dim3(256/64, N_/64, 1), 256>>>(features, Wscalar, nullptr, p_scale,
        N_, L_, D_, D_, L_, L_, 0, 0, 0, 0, 0);

    // 3. edge_norm (windowed renormalized softmax)
    k_edge<<<B_, L_>>>();

    // 4. h_all[n,r,:] = x @ W_rel[r]   (batched z = 8 relations)
    k_gemm<0><<<dim3(H_/64, N_/64, R_), 256>>>(p_em, W_rel, nullptr, p_hall,
        N_, H_, D_, DH_, H_, R_*H_, 0, (long)D_*H_, (long)H_, 0, 0);

    // 5. h1 = x @ W_root + b_rgcn
    k_gemm<0><<<dim3(H_/64, N_/64, 1), 256>>>(p_em, W_root, b_rgcn, p_h1,
        N_, H_, D_, DH_, H_, H_, 0, 0, 0, 0, 0);

    // 6. h1 += RGCN aggregation
    k_rgcn_agg<<<N_, 256>>>(speakers);

    // 7. nbr = neighbor sum of h1
    k_nbr_agg<<<N_, 256>>>();

    // 8./9. h2 = nbr@W_nbr + b_gc + h1@W_self  (written into em[:, D:DH])
    k_gemm<0><<<dim3(H_/64, N_/64, 1), 256>>>(p_nbr, W_nbr, b_gc, p_em + D_,
        N_, H_, H_, H_, H_, DH_, 0, 0, 0, 0, 0);
    k_gemm<0><<<dim3(H_/64, N_/64, 1), 256>>>(p_h1, W_self, nullptr, p_em + D_,
        N_, H_, H_, H_, H_, DH_, 0, 0, 0, 0, 1);

    // 10. xt = em @ W_match + b_match
    k_gemm<0><<<dim3(DH_/64, N_/64, 1), 256>>>(p_em, W_match, b_match, p_xt,
        N_, DH_, DH_, DH_, DH_, DH_, 0, 0, 0, 0, 0);

    // 11. G = tanh(xt_b @ em_b^T), per batch  (NT, batched z = B)
    k_gemm<1><<<dim3(L_/64, L_/64, B_), 256>>>(p_xt, p_em, nullptr, p_G,
        L_, L_, DH_, DH_, DH_, L_, (long)L_*DH_, (long)L_*DH_, (long)L_*L_, 2, 0);

    // 12. softmax rows of G
    k_softmax_g<<<N_, L_>>>();

    // 13. att = G_b @ em_b  (NN, batched)
    k_gemm<0><<<dim3(DH_/64, L_/64, B_), 256>>>(p_G, p_em, nullptr, p_att,
        L_, DH_, L_, L_, DH_, DH_, (long)L_*L_, (long)L_*DH_, (long)L_*DH_, 0, 0);

    // 14. hidden = relu(att @ W_lin + b_lin)
    k_gemm<0><<<dim3(H_/64, N_/64, 1), 256>>>(p_att, W_lin, b_lin, p_hid,
        N_, H_, DH_, DH_, H_, H_, 0, 0, 0, 1, 0);

    // 15. out = log_softmax(hidden @ W_fc + b_fc)
    k_fc<<<(N_*32 + 255)/256, 256>>>(W_fc, b_fc, out);
}

// round 8
// speedup vs baseline: 2.6361x; 2.6361x over previous
#include <cuda_runtime.h>
#include <math.h>
#include <stdint.h>

#define L_    256
#define B_    64
#define D_    1024
#define H_    512
#define R_    8
#define C_    6
#define WIN_  10
#define N_    (B_*L_)
#define DH_   (D_+H_)
#define EPB   5266   // edges per batch (banded window pattern)

// ---------------- scratch (allocation-free: __device__ globals) ----------------
__device__ float g_scale [(size_t)N_*L_];     // [ (s*B+b), i ]  16 MB
__device__ float g_edge  [(size_t)B_*EPB];    // edge_norm        1.35 MB
__device__ float g_em    [(size_t)N_*DH_];    // [n, x|h2]        96 MB
__device__ float g_hall  [(size_t)N_*R_*H_];  // [n, r, h]        256 MB
__device__ float g_h1    [(size_t)N_*H_];
__device__ float g_nbr   [(size_t)N_*H_];
__device__ float g_xt    [(size_t)N_*DH_];
__device__ float g_G     [(size_t)B_*L_*L_];  // attention logits/probs
__device__ float g_att   [(size_t)N_*DH_];
__device__ float g_hid   [(size_t)N_*H_];

// edges with anchor j < i  (edges(j) = min(255,j+10)-max(0,j-10)+1)
__device__ __forceinline__ int edge_prefix(int i) {
    if (i <= 10)  return i*11 + (i*(i-1))/2;
    if (i <= 246) return 155 + (i-10)*21;
    int t = i - 246;
    return 5111 + 20*t - (t*(t-1))/2;
}

// ---------------- em[:, 0:D] = x  (node-major transpose of features) ----------------
__global__ void k_embed_x(const float* __restrict__ f) {
    int j = blockIdx.x, b = blockIdx.y;
    const float4* src = reinterpret_cast<const float4*>(f + ((size_t)j*B_ + b)*D_);
    float4* dst = reinterpret_cast<float4*>(g_em + ((size_t)b*L_ + j)*DH_);
    dst[threadIdx.x] = src[threadIdx.x];   // 256 threads * float4 = 1024 floats
}

// ---------------- edge_norm: windowed renormalized softmax ----------------
__global__ void k_edge() {
    int b = blockIdx.x;
    int i = threadIdx.x;                 // anchor
    int ks = max(0, i - WIN_), ke = min(L_-1, i + WIN_);
    float wv[2*WIN_ + 1];
    float m = -1e30f, S = 0.f;
    for (int s = 0; s < L_; s++) {
        float v = __ldg(g_scale + ((size_t)s*B_ + b)*L_ + i);
        float mn = fmaxf(m, v);
        S = S*__expf(m - mn) + __expf(v - mn);
        m = mn;
        if (s >= ks && s <= ke) wv[s - ks] = v;
    }
    int cnt = ke - ks + 1;
    float Sw = 0.f;
    for (int t = 0; t < cnt; t++) { wv[t] = __expf(wv[t] - m); Sw += wv[t]; }
    float inv = 1.f / (Sw + 1e-10f*(S - Sw));
    float* out = g_edge + (size_t)b*EPB + edge_prefix(i);
    for (int t = 0; t < cnt; t++) out[t] = wv[t]*inv;
}

// ---------------- RGCN aggregation: h1[dst] += sum_e w_e * h_all[src, rel] ----------------
__global__ void k_rgcn_agg(const int* __restrict__ sp) {
    int n = blockIdx.x;
    int b = n / L_, k = n % L_;          // dst = (b, k)
    int spk = __ldg(sp + k*B_ + b);
    int t = threadIdx.x;                  // 256 threads, 2 h each
    float a0 = 0.f, a1 = 0.f;
    int is = max(0, k - WIN_), ie = min(L_-1, k + WIN_);
    for (int i = is; i <= ie; i++) {
        float w = __ldg(g_edge + (size_t)b*EPB + edge_prefix(i) + (k - max(0, i - WIN_)));
        int spi = __ldg(sp + i*B_ + b);
        int r = spi*4 + spk*2 + ((i < k) ? 0 : 1);
        const float* row = g_hall + (((size_t)(b*L_ + i))*R_ + r)*H_;
        a0 += w*__ldg(row + t);
        a1 += w*__ldg(row + t + 256);
    }
    g_h1[(size_t)n*H_ + t]       += a0;
    g_h1[(size_t)n*H_ + t + 256] += a1;
}

// ---------------- GraphConv neighbor sum ----------------
__global__ void k_nbr_agg() {
    int n = blockIdx.x;
    int b = n / L_, k = n % L_;
    int t = threadIdx.x;
    float a0 = 0.f, a1 = 0.f;
    int is = max(0, k - WIN_), ie = min(L_-1, k + WIN_);
    for (int i = is; i <= ie; i++) {
        const float* row = g_h1 + (size_t)(b*L_ + i)*H_;
        a0 += __ldg(row + t);
        a1 += __ldg(row + t + 256);
    }
    g_nbr[(size_t)n*H_ + t]       = a0;
    g_nbr[(size_t)n*H_ + t + 256] = a1;
}

// ================= TF32 tensor-core GEMM =================
// C(MxN) = A(MxK) * B(KxN)  (TRANSB: B stored (N,K) row-major)
// block tile 128x128x16, 8 warps, warp tile 64x32, mma.m16n8k8.tf32

__device__ __forceinline__ uint32_t f2tf(float x) {
    uint32_t u; asm("cvt.rna.tf32.f32 %0, %1;" : "=r"(u) : "f"(x)); return u;
}

__device__ __forceinline__ void mma8(float* c, const uint32_t* a, const uint32_t* b) {
    asm volatile("mma.sync.aligned.m16n8k8.row.col.f32.tf32.tf32.f32 "
        "{%0,%1,%2,%3}, {%4,%5,%6,%7}, {%8,%9}, {%0,%1,%2,%3};"
        : "+f"(c[0]), "+f"(c[1]), "+f"(c[2]), "+f"(c[3])
        : "r"(a[0]), "r"(a[1]), "r"(a[2]), "r"(a[3]), "r"(b[0]), "r"(b[1]));
}

#define BM 128
#define BN 128
#define BK 16
#define SSTR 136   // padded row stride (words): conflict-free fragment LDS

template<int TRANSB>
__global__ void __launch_bounds__(256, 2)
k_gemm_tc(const float* __restrict__ A, const float* __restrict__ Bm,
          const float* __restrict__ bias, float* __restrict__ Cm,
          int M, int N, int K, int lda, int ldb, int ldc,
          long sA, long sB, long sC, int epi, int accum)
{
    __shared__ uint32_t As[BK*SSTR];
    __shared__ uint32_t Bs[BK*SSTR];
    int z = blockIdx.z;
    A  += (size_t)z * sA;
    Bm += (size_t)z * sB;
    Cm += (size_t)z * sC;
    const int m0 = blockIdx.y * BM, n0 = blockIdx.x * BN;
    const int tid = threadIdx.x;
    const int warp = tid >> 5, lane = tid & 31;
    const int g = lane >> 2, t = lane & 3;
    const int wm0 = (warp >> 2) * 64;   // warp row offset within block tile
    const int wn0 = (warp & 3) * 32;    // warp col offset

    // ---- global load mapping: each thread loads 8 contiguous floats of A and B
    const int a_m  = tid >> 1;            // 0..127
    const int a_kb = (tid & 1) * 8;       // 0 or 8
    const float* Ap = A + (size_t)(m0 + a_m)*lda + a_kb;

    const float* Bp;
    int b_r, b_c;                          // smem dest (row k, col n) base
    if (TRANSB == 0) {
        int bk = tid >> 4;                 // 0..15
        int bn = (tid & 15) * 8;           // 0..120
        Bp = Bm + (size_t)bk*ldb + n0 + bn;
        b_r = bk; b_c = bn;
    } else {
        int bn = tid >> 1;                 // 0..127 (row of B = output col)
        int bkb = (tid & 1) * 8;
        Bp = Bm + (size_t)(n0 + bn)*ldb + bkb;
        b_r = bkb; b_c = bn;
    }

    float acc[4][4][4];
#pragma unroll
    for (int mi = 0; mi < 4; mi++)
#pragma unroll
        for (int ni = 0; ni < 4; ni++)
#pragma unroll
            for (int j = 0; j < 4; j++) acc[mi][ni][j] = 0.f;

    // prologue loads
    float4 pa0 = *reinterpret_cast<const float4*>(Ap);
    float4 pa1 = *reinterpret_cast<const float4*>(Ap + 4);
    float4 pb0 = *reinterpret_cast<const float4*>(Bp);
    float4 pb1 = *reinterpret_cast<const float4*>(Bp + 4);

    const int niter = K / BK;
    for (int it = 0; it < niter; it++) {
        // ---- store current tile to smem (cvt to tf32)
        {
            uint32_t* a = As + a_m + a_kb*SSTR;
            a[0*SSTR]=f2tf(pa0.x); a[1*SSTR]=f2tf(pa0.y); a[2*SSTR]=f2tf(pa0.z); a[3*SSTR]=f2tf(pa0.w);
            a[4*SSTR]=f2tf(pa1.x); a[5*SSTR]=f2tf(pa1.y); a[6*SSTR]=f2tf(pa1.z); a[7*SSTR]=f2tf(pa1.w);
            if (TRANSB == 0) {
                uint32_t* b = Bs + b_r*SSTR + b_c;
                b[0]=f2tf(pb0.x); b[1]=f2tf(pb0.y); b[2]=f2tf(pb0.z); b[3]=f2tf(pb0.w);
                b[4]=f2tf(pb1.x); b[5]=f2tf(pb1.y); b[6]=f2tf(pb1.z); b[7]=f2tf(pb1.w);
            } else {
                uint32_t* b = Bs + b_c + b_r*SSTR;
                b[0*SSTR]=f2tf(pb0.x); b[1*SSTR]=f2tf(pb0.y); b[2*SSTR]=f2tf(pb0.z); b[3*SSTR]=f2tf(pb0.w);
                b[4*SSTR]=f2tf(pb1.x); b[5*SSTR]=f2tf(pb1.y); b[6*SSTR]=f2tf(pb1.z); b[7*SSTR]=f2tf(pb1.w);
            }
        }
        __syncthreads();

        // ---- prefetch next tile (overlaps with mma compute)
        if (it + 1 < niter) {
            Ap += BK;
            if (TRANSB == 0) Bp += (size_t)BK * ldb; else Bp += BK;
            pa0 = *reinterpret_cast<const float4*>(Ap);
            pa1 = *reinterpret_cast<const float4*>(Ap + 4);
            pb0 = *reinterpret_cast<const float4*>(Bp);
            pb1 = *reinterpret_cast<const float4*>(Bp + 4);
        }

        // ---- compute: two k8 sub-steps
#pragma unroll
        for (int ks = 0; ks < BK; ks += 8) {
            uint32_t af[4][4], bf[4][2];
#pragma unroll
            for (int mi = 0; mi < 4; mi++) {
                int r = wm0 + mi*16 + g;
                af[mi][0] = As[(ks + t    )*SSTR + r];
                af[mi][1] = As[(ks + t    )*SSTR + r + 8];
                af[mi][2] = As[(ks + t + 4)*SSTR + r];
                af[mi][3] = As[(ks + t + 4)*SSTR + r + 8];
            }
#pragma unroll
            for (int ni = 0; ni < 4; ni++) {
                int c = wn0 + ni*8 + g;
                bf[ni][0] = Bs[(ks + t    )*SSTR + c];
                bf[ni][1] = Bs[(ks + t + 4)*SSTR + c];
            }
#pragma unroll
            for (int mi = 0; mi < 4; mi++)
#pragma unroll
                for (int ni = 0; ni < 4; ni++)
                    mma8(acc[mi][ni], af[mi], bf[ni]);
        }
        __syncthreads();
    }

    // ---- epilogue
#pragma unroll
    for (int mi = 0; mi < 4; mi++) {
#pragma unroll
        for (int ni = 0; ni < 4; ni++) {
            int row = m0 + wm0 + mi*16 + g;
            int col = n0 + wn0 + ni*8 + t*2;
            float b0 = 0.f, b1 = 0.f;
            if (bias) { b0 = __ldg(bias + col); b1 = __ldg(bias + col + 1); }
#pragma unroll
            for (int h = 0; h < 2; h++) {     // h=0: row, h=1: row+8
                int rr = row + h*8;
                float v0 = acc[mi][ni][h*2+0];
                float v1 = acc[mi][ni][h*2+1];
                float* p = Cm + (size_t)rr*ldc + col;
                if (accum) { float2 old = *reinterpret_cast<float2*>(p); v0 += old.x; v1 += old.y; }
                v0 += b0; v1 += b1;
                if (epi == 1)      { v0 = fmaxf(v0, 0.f); v1 = fmaxf(v1, 0.f); }
                else if (epi == 2) { v0 = tanhf(v0);      v1 = tanhf(v1); }
                float2 w; w.x = v0; w.y = v1;
                *reinterpret_cast<float2*>(p) = w;
            }
        }
    }
}

// ---------------- row softmax over G (256 cols) ----------------
__global__ void k_softmax_g() {
    int row = blockIdx.x;                 // b*L + t
    float* p = g_G + (size_t)row*L_;
    int t = threadIdx.x;
    __shared__ float red[256];
    float v = p[t];
    red[t] = v; __syncthreads();
    for (int s = 128; s > 0; s >>= 1) { if (t < s) red[t] = fmaxf(red[t], red[t+s]); __syncthreads(); }
    float m = red[0]; __syncthreads();
    float e = __expf(v - m);
    red[t] = e; __syncthreads();
    for (int s = 128; s > 0; s >>= 1) { if (t < s) red[t] += red[t+s]; __syncthreads(); }
    p[t] = e / red[0];
}

// ---------------- fc + log_softmax (warp per node) ----------------
__global__ void k_fc(const float* __restrict__ Wfc, const float* __restrict__ bfc,
                     float* __restrict__ out) {
    int warp = (blockIdx.x * blockDim.x + threadIdx.x) >> 5;
    int lane = threadIdx.x & 31;
    if (warp >= N_) return;
    const float* h = g_hid + (size_t)warp*H_;
    float acc[6] = {0,0,0,0,0,0};
    for (int k = lane; k < H_; k += 32) {
        float hv = __ldg(h + k);
        const float* w = Wfc + k*C_;
#pragma unroll
        for (int c = 0; c < C_; c++) acc[c] += hv * __ldg(w + c);
    }
#pragma unroll
    for (int c = 0; c < C_; c++)
#pragma unroll
        for (int o = 16; o > 0; o >>= 1) acc[c] += __shfl_xor_sync(0xffffffffu, acc[c], o);
    if (lane == 0) {
        float z[6], m = -1e30f;
#pragma unroll
        for (int c = 0; c < C_; c++) { z[c] = acc[c] + __ldg(bfc + c); m = fmaxf(m, z[c]); }
        float s = 0.f;
#pragma unroll
        for (int c = 0; c < C_; c++) s += expf(z[c] - m);
        float lse = logf(s);
#pragma unroll
        for (int c = 0; c < C_; c++) out[(size_t)warp*C_ + c] = z[c] - m - lse;
    }
}

// ---------------- host ----------------
static float* sym_addr(const void* symbol) {
    void* p = nullptr;
    cudaGetSymbolAddress(&p, symbol);
    return (float*)p;
}

extern "C" void kernel_launch(void* const* d_in, const int* in_sizes, int n_in,
                              void* d_out, int out_size) {
    const float* features = (const float*)d_in[0];
    const float* Wscalar  = (const float*)d_in[1];
    const float* W_rel    = (const float*)d_in[2];
    const float* W_root   = (const float*)d_in[3];
    const float* b_rgcn   = (const float*)d_in[4];
    const float* W_nbr    = (const float*)d_in[5];
    const float* W_self   = (const float*)d_in[6];
    const float* b_gc     = (const float*)d_in[7];
    const float* W_match  = (const float*)d_in[8];
    const float* b_match  = (const float*)d_in[9];
    const float* W_lin    = (const float*)d_in[10];
    const float* b_lin    = (const float*)d_in[11];
    const float* W_fc     = (const float*)d_in[12];
    const float* b_fc     = (const float*)d_in[13];
    const int*   speakers = (const int*)d_in[14];
    float* out = (float*)d_out;

    float* p_scale = sym_addr(g_scale);
    float* p_em    = sym_addr(g_em);
    float* p_hall  = sym_addr(g_hall);
    float* p_h1    = sym_addr(g_h1);
    float* p_nbr   = sym_addr(g_nbr);
    float* p_xt    = sym_addr(g_xt);
    float* p_G     = sym_addr(g_G);
    float* p_att   = sym_addr(g_att);
    float* p_hid   = sym_addr(g_hid);

    // 1. em[:, 0:D] = x (node-major features)
    k_embed_x<<<dim3(L_, B_), 256>>>(features);

    // 2. scale = features_flat(16384x1024) @ Wscalar(1024x256)
    k_gemm_tc<0><<<dim3(L_/BN, N_/BM, 1), 256>>>(features, Wscalar, nullptr, p_scale,
        N_, L_, D_, D_, L_, L_, 0, 0, 0, 0, 0);

    // 3. edge_norm (windowed renormalized softmax)
    k_edge<<<B_, L_>>>();

    // 4. h_all[n,r,:] = x @ W_rel[r]   (batched z = 8 relations)
    k_gemm_tc<0><<<dim3(H_/BN, N_/BM, R_), 256>>>(p_em, W_rel, nullptr, p_hall,
        N_, H_, D_, DH_, H_, R_*H_, 0, (long)D_*H_, (long)H_, 0, 0);

    // 5. h1 = x @ W_root + b_rgcn
    k_gemm_tc<0><<<dim3(H_/BN, N_/BM, 1), 256>>>(p_em, W_root, b_rgcn, p_h1,
        N_, H_, D_, DH_, H_, H_, 0, 0, 0, 0, 0);

    // 6. h1 += RGCN aggregation
    k_rgcn_agg<<<N_, 256>>>(speakers);

    // 7. nbr = neighbor sum of h1
    k_nbr_agg<<<N_, 256>>>();

    // 8./9. h2 = nbr@W_nbr + b_gc + h1@W_self  (written into em[:, D:DH])
    k_gemm_tc<0><<<dim3(H_/BN, N_/BM, 1), 256>>>(p_nbr, W_nbr, b_gc, p_em + D_,
        N_, H_, H_, H_, H_, DH_, 0, 0, 0, 0, 0);
    k_gemm_tc<0><<<dim3(H_/BN, N_/BM, 1), 256>>>(p_h1, W_self, nullptr, p_em + D_,
        N_, H_, H_, H_, H_, DH_, 0, 0, 0, 0, 1);

    // 10. xt = em @ W_match + b_match
    k_gemm_tc<0><<<dim3(DH_/BN, N_/BM, 1), 256>>>(p_em, W_match, b_match, p_xt,
        N_, DH_, DH_, DH_, DH_, DH_, 0, 0, 0, 0, 0);

    // 11. G = tanh(xt_b @ em_b^T), per batch  (NT, batched z = B)
    k_gemm_tc<1><<<dim3(L_/BN, L_/BM, B_), 256>>>(p_xt, p_em, nullptr, p_G,
        L_, L_, DH_, DH_, DH_, L_, (long)L_*DH_, (long)L_*DH_, (long)L_*L_, 2, 0);

    // 12. softmax rows of G
    k_softmax_g<<<N_, L_>>>();

    // 13. att = G_b @ em_b  (NN, batched)
    k_gemm_tc<0><<<dim3(DH_/BN, L_/BM, B_), 256>>>(p_G, p_em, nullptr, p_att,
        L_, DH_, L_, L_, DH_, DH_, (long)L_*L_, (long)L_*DH_, (long)L_*DH_, 0, 0);

    // 14. hidden = relu(att @ W_lin + b_lin)
    k_gemm_tc<0><<<dim3(H_/BN, N_/BM, 1), 256>>>(p_att, W_lin, b_lin, p_hid,
        N_, H_, DH_, DH_, H_, H_, 0, 0, 0, 1, 0);

    // 15. out = log_softmax(hidden @ W_fc + b_fc)
    k_fc<<<(N_*32 + 255)/256, 256>>>(W_fc, b_fc, out);
}

// round 13
// speedup vs baseline: 2.6377x; 1.0006x over previous
#include <cuda_runtime.h>
#include <math.h>
#include <stdint.h>

#define L_    256
#define B_    64
#define D_    1024
#define H_    512
#define R_    8
#define C_    6
#define WIN_  10
#define N_    (B_*L_)
#define DH_   (D_+H_)
#define EPB   5266   // edges per batch (banded window pattern)

// ---------------- scratch (allocation-free: __device__ globals) ----------------
__device__ float g_scale [(size_t)N_*L_];     // [ (s*B+b), i ]  16 MB
__device__ float g_edge  [(size_t)B_*EPB];    // edge_norm        1.35 MB
__device__ float g_em    [(size_t)N_*DH_];    // [n, x|h2]        96 MB
__device__ float g_hall  [(size_t)N_*R_*H_];  // [n, r, h]        256 MB
__device__ float g_h1    [(size_t)N_*H_];
__device__ float g_nbr   [(size_t)N_*H_];
__device__ float g_xt    [(size_t)N_*DH_];
__device__ float g_G     [(size_t)B_*L_*L_];  // attention logits/probs
__device__ float g_att   [(size_t)N_*DH_];
__device__ float g_hid   [(size_t)N_*H_];

// edges with anchor j < i  (edges(j) = min(255,j+10)-max(0,j-10)+1)
__device__ __forceinline__ int edge_prefix(int i) {
    if (i <= 10)  return i*11 + (i*(i-1))/2;
    if (i <= 246) return 155 + (i-10)*21;
    int t = i - 246;
    return 5111 + 20*t - (t*(t-1))/2;
}

// ---------------- em[:, 0:D] = x  (node-major transpose of features) ----------------
__global__ void k_embed_x(const float* __restrict__ f) {
    int j = blockIdx.x, b = blockIdx.y;
    const float4* src = reinterpret_cast<const float4*>(f + ((size_t)j*B_ + b)*D_);
    float4* dst = reinterpret_cast<float4*>(g_em + ((size_t)b*L_ + j)*DH_);
    dst[threadIdx.x] = src[threadIdx.x];   // 256 threads * float4 = 1024 floats
}

// ---------------- edge_norm: windowed renormalized softmax ----------------
__global__ void k_edge() {
    int b = blockIdx.x;
    int i = threadIdx.x;                 // anchor
    int ks = max(0, i - WIN_), ke = min(L_-1, i + WIN_);
    float wv[2*WIN_ + 1];
    float m = -1e30f, S = 0.f;
    for (int s = 0; s < L_; s++) {
        float v = __ldg(g_scale + ((size_t)s*B_ + b)*L_ + i);
        float mn = fmaxf(m, v);
        S = S*__expf(m - mn) + __expf(v - mn);
        m = mn;
        if (s >= ks && s <= ke) wv[s - ks] = v;
    }
    int cnt = ke - ks + 1;
    float Sw = 0.f;
    for (int t = 0; t < cnt; t++) { wv[t] = __expf(wv[t] - m); Sw += wv[t]; }
    float inv = 1.f / (Sw + 1e-10f*(S - Sw));
    float* out = g_edge + (size_t)b*EPB + edge_prefix(i);
    for (int t = 0; t < cnt; t++) out[t] = wv[t]*inv;
}

// ---------------- RGCN aggregation: h1[dst] += sum_e w_e * h_all[src, rel] ----------------
__global__ void k_rgcn_agg(const int* __restrict__ sp) {
    int n = blockIdx.x;
    int b = n / L_, k = n % L_;          // dst = (b, k)
    int spk = __ldg(sp + k*B_ + b);
    int t = threadIdx.x;                  // 256 threads, 2 h each
    float a0 = 0.f, a1 = 0.f;
    int is = max(0, k - WIN_), ie = min(L_-1, k + WIN_);
    for (int i = is; i <= ie; i++) {
        float w = __ldg(g_edge + (size_t)b*EPB + edge_prefix(i) + (k - max(0, i - WIN_)));
        int spi = __ldg(sp + i*B_ + b);
        int r = spi*4 + spk*2 + ((i < k) ? 0 : 1);
        const float* row = g_hall + (((size_t)(b*L_ + i))*R_ + r)*H_;
        a0 += w*__ldg(row + t);
        a1 += w*__ldg(row + t + 256);
    }
    g_h1[(size_t)n*H_ + t]       += a0;
    g_h1[(size_t)n*H_ + t + 256] += a1;
}

// ---------------- GraphConv neighbor sum ----------------
__global__ void k_nbr_agg() {
    int n = blockIdx.x;
    int b = n / L_, k = n % L_;
    int t = threadIdx.x;
    float a0 = 0.f, a1 = 0.f;
    int is = max(0, k - WIN_), ie = min(L_-1, k + WIN_);
    for (int i = is; i <= ie; i++) {
        const float* row = g_h1 + (size_t)(b*L_ + i)*H_;
        a0 += __ldg(row + t);
        a1 += __ldg(row + t + 256);
    }
    g_nbr[(size_t)n*H_ + t]       = a0;
    g_nbr[(size_t)n*H_ + t + 256] = a1;
}

// ================= TF32 tensor-core GEMM =================
// C(MxN) = A(MxK) * B(KxN)  (TRANSB: B stored (N,K) row-major)
// block tile 128x128x16, 8 warps, warp tile 64x32, mma.m16n8k8.tf32

__device__ __forceinline__ uint32_t f2tf(float x) {
    uint32_t u; asm("cvt.rna.tf32.f32 %0, %1;" : "=r"(u) : "f"(x)); return u;
}

__device__ __forceinline__ void mma8(float* c, const uint32_t* a, const uint32_t* b) {
    asm volatile("mma.sync.aligned.m16n8k8.row.col.f32.tf32.tf32.f32 "
        "{%0,%1,%2,%3}, {%4,%5,%6,%7}, {%8,%9}, {%0,%1,%2,%3};"
        : "+f"(c[0]), "+f"(c[1]), "+f"(c[2]), "+f"(c[3])
        : "r"(a[0]), "r"(a[1]), "r"(a[2]), "r"(a[3]), "r"(b[0]), "r"(b[1]));
}

#define BM 128
#define BN 128
#define BK 16
#define SSTR 136   // padded row stride (words): conflict-free fragment LDS

template<int TRANSB>
__global__ void __launch_bounds__(256, 2)
k_gemm_tc(const float* __restrict__ A, const float* __restrict__ Bm,
          const float* __restrict__ bias, float* __restrict__ Cm,
          int M, int N, int K, int lda, int ldb, int ldc,
          long sA, long sB, long sC, int epi, int accum)
{
    __shared__ uint32_t As[BK*SSTR];
    __shared__ uint32_t Bs[BK*SSTR];
    int z = blockIdx.z;
    A  += (size_t)z * sA;
    Bm += (size_t)z * sB;
    Cm += (size_t)z * sC;
    const int m0 = blockIdx.y * BM, n0 = blockIdx.x * BN;
    const int tid = threadIdx.x;
    const int warp = tid >> 5, lane = tid & 31;
    const int g = lane >> 2, t = lane & 3;
    const int wm0 = (warp >> 2) * 64;   // warp row offset within block tile
    const int wn0 = (warp & 3) * 32;    // warp col offset

    // ---- global load mapping: each thread loads 8 contiguous floats of A and B
    const int a_m  = tid >> 1;            // 0..127
    const int a_kb = (tid & 1) * 8;       // 0 or 8
    const float* Ap = A + (size_t)(m0 + a_m)*lda + a_kb;

    const float* Bp;
    int b_r, b_c;                          // smem dest (row k, col n) base
    if (TRANSB == 0) {
        int bk = tid >> 4;                 // 0..15
        int bn = (tid & 15) * 8;           // 0..120
        Bp = Bm + (size_t)bk*ldb + n0 + bn;
        b_r = bk; b_c = bn;
    } else {
        int bn = tid >> 1;                 // 0..127 (row of B = output col)
        int bkb = (tid & 1) * 8;
        Bp = Bm + (size_t)(n0 + bn)*ldb + bkb;
        b_r = bkb; b_c = bn;
    }

    float acc[4][4][4];
#pragma unroll
    for (int mi = 0; mi < 4; mi++)
#pragma unroll
        for (int ni = 0; ni < 4; ni++)
#pragma unroll
            for (int j = 0; j < 4; j++) acc[mi][ni][j] = 0.f;

    // prologue loads
    float4 pa0 = *reinterpret_cast<const float4*>(Ap);
    float4 pa1 = *reinterpret_cast<const float4*>(Ap + 4);
    float4 pb0 = *reinterpret_cast<const float4*>(Bp);
    float4 pb1 = *reinterpret_cast<const float4*>(Bp + 4);

    const int niter = K / BK;
    for (int it = 0; it < niter; it++) {
        // ---- store current tile to smem (cvt to tf32)
        {
            uint32_t* a = As + a_m + a_kb*SSTR;
            a[0*SSTR]=f2tf(pa0.x); a[1*SSTR]=f2tf(pa0.y); a[2*SSTR]=f2tf(pa0.z); a[3*SSTR]=f2tf(pa0.w);
            a[4*SSTR]=f2tf(pa1.x); a[5*SSTR]=f2tf(pa1.y); a[6*SSTR]=f2tf(pa1.z); a[7*SSTR]=f2tf(pa1.w);
            if (TRANSB == 0) {
                uint32_t* b = Bs + b_r*SSTR + b_c;
                b[0]=f2tf(pb0.x); b[1]=f2tf(pb0.y); b[2]=f2tf(pb0.z); b[3]=f2tf(pb0.w);
                b[4]=f2tf(pb1.x); b[5]=f2tf(pb1.y); b[6]=f2tf(pb1.z); b[7]=f2tf(pb1.w);
            } else {
                uint32_t* b = Bs + b_c + b_r*SSTR;
                b[0*SSTR]=f2tf(pb0.x); b[1*SSTR]=f2tf(pb0.y); b[2*SSTR]=f2tf(pb0.z); b[3*SSTR]=f2tf(pb0.w);
                b[4*SSTR]=f2tf(pb1.x); b[5*SSTR]=f2tf(pb1.y); b[6*SSTR]=f2tf(pb1.z); b[7*SSTR]=f2tf(pb1.w);
            }
        }
        __syncthreads();

        // ---- prefetch next tile (overlaps with mma compute)
        if (it + 1 < niter) {
            Ap += BK;
            if (TRANSB == 0) Bp += (size_t)BK * ldb; else Bp += BK;
            pa0 = *reinterpret_cast<const float4*>(Ap);
            pa1 = *reinterpret_cast<const float4*>(Ap + 4);
            pb0 = *reinterpret_cast<const float4*>(Bp);
            pb1 = *reinterpret_cast<const float4*>(Bp + 4);
        }

        // ---- compute: two k8 sub-steps
#pragma unroll
        for (int ks = 0; ks < BK; ks += 8) {
            uint32_t af[4][4], bf[4][2];
#pragma unroll
            for (int mi = 0; mi < 4; mi++) {
                int r = wm0 + mi*16 + g;
                af[mi][0] = As[(ks + t    )*SSTR + r];
                af[mi][1] = As[(ks + t    )*SSTR + r + 8];
                af[mi][2] = As[(ks + t + 4)*SSTR + r];
                af[mi][3] = As[(ks + t + 4)*SSTR + r + 8];
            }
#pragma unroll
            for (int ni = 0; ni < 4; ni++) {
                int c = wn0 + ni*8 + g;
                bf[ni][0] = Bs[(ks + t    )*SSTR + c];
                bf[ni][1] = Bs[(ks + t + 4)*SSTR + c];
            }
#pragma unroll
            for (int mi = 0; mi < 4; mi++)
#pragma unroll
                for (int ni = 0; ni < 4; ni++)
                    mma8(acc[mi][ni], af[mi], bf[ni]);
        }
        __syncthreads();
    }

    // ---- epilogue
#pragma unroll
    for (int mi = 0; mi < 4; mi++) {
#pragma unroll
        for (int ni = 0; ni < 4; ni++) {
            int row = m0 + wm0 + mi*16 + g;
            int col = n0 + wn0 + ni*8 + t*2;
            float b0 = 0.f, b1 = 0.f;
            if (bias) { b0 = __ldg(bias + col); b1 = __ldg(bias + col + 1); }
#pragma unroll
            for (int h = 0; h < 2; h++) {     // h=0: row, h=1: row+8
                int rr = row + h*8;
                float v0 = acc[mi][ni][h*2+0];
                float v1 = acc[mi][ni][h*2+1];
                float* p = Cm + (size_t)rr*ldc + col;
                if (accum) { float2 old = *reinterpret_cast<float2*>(p); v0 += old.x; v1 += old.y; }
                v0 += b0; v1 += b1;
                if (epi == 1)      { v0 = fmaxf(v0, 0.f); v1 = fmaxf(v1, 0.f); }
                else if (epi == 2) { v0 = tanhf(v0);      v1 = tanhf(v1); }
                float2 w; w.x = v0; w.y = v1;
                *reinterpret_cast<float2*>(p) = w;
            }
        }
    }
}

// ---------------- row softmax over G (256 cols) ----------------
__global__ void k_softmax_g() {
    int row = blockIdx.x;                 // b*L + t
    float* p = g_G + (size_t)row*L_;
    int t = threadIdx.x;
    __shared__ float red[256];
    float v = p[t];
    red[t] = v; __syncthreads();
    for (int s = 128; s > 0; s >>= 1) { if (t < s) red[t] = fmaxf(red[t], red[t+s]); __syncthreads(); }
    float m = red[0]; __syncthreads();
    float e = __expf(v - m);
    red[t] = e; __syncthreads();
    for (int s = 128; s > 0; s >>= 1) { if (t < s) red[t] += red[t+s]; __syncthreads(); }
    p[t] = e / red[0];
}

// ---------------- fc + log_softmax (warp per node) ----------------
__global__ void k_fc(const float* __restrict__ Wfc, const float* __restrict__ bfc,
                     float* __restrict__ out) {
    int warp = (blockIdx.x * blockDim.x + threadIdx.x) >> 5;
    int lane = threadIdx.x & 31;
    if (warp >= N_) return;
    const float* h = g_hid + (size_t)warp*H_;
    float acc[6] = {0,0,0,0,0,0};
    for (int k = lane; k < H_; k += 32) {
        float hv = __ldg(h + k);
        const float* w = Wfc + k*C_;
#pragma unroll
        for (int c = 0; c < C_; c++) acc[c] += hv * __ldg(w + c);
    }
#pragma unroll
    for (int c = 0; c < C_; c++)
#pragma unroll
        for (int o = 16; o > 0; o >>= 1) acc[c] += __shfl_xor_sync(0xffffffffu, acc[c], o);
    if (lane == 0) {
        float z[6], m = -1e30f;
#pragma unroll
        for (int c = 0; c < C_; c++) { z[c] = acc[c] + __ldg(bfc + c); m = fmaxf(m, z[c]); }
        float s = 0.f;
#pragma unroll
        for (int c = 0; c < C_; c++) s += expf(z[c] - m);
        float lse = logf(s);
#pragma unroll
        for (int c = 0; c < C_; c++) out[(size_t)warp*C_ + c] = z[c] - m - lse;
    }
}

// ---------------- host ----------------
static float* sym_addr(const void* symbol) {
    void* p = nullptr;
    cudaGetSymbolAddress(&p, symbol);
    return (float*)p;
}

extern "C" void kernel_launch(void* const* d_in, const int* in_sizes, int n_in,
                              void* d_out, int out_size) {
    const float* features = (const float*)d_in[0];
    const float* Wscalar  = (const float*)d_in[1];
    const float* W_rel    = (const float*)d_in[2];
    const float* W_root   = (const float*)d_in[3];
    const float* b_rgcn   = (const float*)d_in[4];
    const float* W_nbr    = (const float*)d_in[5];
    const float* W_self   = (const float*)d_in[6];
    const float* b_gc     = (const float*)d_in[7];
    const float* W_match  = (const float*)d_in[8];
    const float* b_match  = (const float*)d_in[9];
    const float* W_lin    = (const float*)d_in[10];
    const float* b_lin    = (const float*)d_in[11];
    const float* W_fc     = (const float*)d_in[12];
    const float* b_fc     = (const float*)d_in[13];
    const int*   speakers = (const int*)d_in[14];
    float* out = (float*)d_out;

    float* p_scale = sym_addr(g_scale);
    float* p_em    = sym_addr(g_em);
    float* p_hall  = sym_addr(g_hall);
    float* p_h1    = sym_addr(g_h1);
    float* p_nbr   = sym_addr(g_nbr);
    float* p_xt    = sym_addr(g_xt);
    float* p_G     = sym_addr(g_G);
    float* p_att   = sym_addr(g_att);
    float* p_hid   = sym_addr(g_hid);

    // 1. em[:, 0:D] = x (node-major features)
    k_embed_x<<<dim3(L_, B_), 256>>>(features);

    // 2. scale = features_flat(16384x1024) @ Wscalar(1024x256)
    k_gemm_tc<0><<<dim3(L_/BN, N_/BM, 1), 256>>>(features, Wscalar, nullptr, p_scale,
        N_, L_, D_, D_, L_, L_, 0, 0, 0, 0, 0);

    // 3. edge_norm (windowed renormalized softmax)
    k_edge<<<B_, L_>>>();

    // 4. h_all[n,r,:] = x @ W_rel[r]   (batched z = 8 relations)
    k_gemm_tc<0><<<dim3(H_/BN, N_/BM, R_), 256>>>(p_em, W_rel, nullptr, p_hall,
        N_, H_, D_, DH_, H_, R_*H_, 0, (long)D_*H_, (long)H_, 0, 0);

    // 5. h1 = x @ W_root + b_rgcn
    k_gemm_tc<0><<<dim3(H_/BN, N_/BM, 1), 256>>>(p_em, W_root, b_rgcn, p_h1,
        N_, H_, D_, DH_, H_, H_, 0, 0, 0, 0, 0);

    // 6. h1 += RGCN aggregation
    k_rgcn_agg<<<N_, 256>>>(speakers);

    // 7. nbr = neighbor sum of h1
    k_nbr_agg<<<N_, 256>>>();

    // 8./9. h2 = nbr@W_nbr + b_gc + h1@W_self  (written into em[:, D:DH])
    k_gemm_tc<0><<<dim3(H_/BN, N_/BM, 1), 256>>>(p_nbr, W_nbr, b_gc, p_em + D_,
        N_, H_, H_, H_, H_, DH_, 0, 0, 0, 0, 0);
    k_gemm_tc<0><<<dim3(H_/BN, N_/BM, 1), 256>>>(p_h1, W_self, nullptr, p_em + D_,
        N_, H_, H_, H_, H_, DH_, 0, 0, 0, 0, 1);

    // 10. xt = em @ W_match + b_match
    k_gemm_tc<0><<<dim3(DH_/BN, N_/BM, 1), 256>>>(p_em, W_match, b_match, p_xt,
        N_, DH_, DH_, DH_, DH_, DH_, 0, 0, 0, 0, 0);

    // 11. G = tanh(xt_b @ em_b^T), per batch  (NT, batched z = B)
    k_gemm_tc<1><<<dim3(L_/BN, L_/BM, B_), 256>>>(p_xt, p_em, nullptr, p_G,
        L_, L_, DH_, DH_, DH_, L_, (long)L_*DH_, (long)L_*DH_, (long)L_*L_, 2, 0);

    // 12. softmax rows of G
    k_softmax_g<<<N_, L_>>>();

    // 13. att = G_b @ em_b  (NN, batched)
    k_gemm_tc<0><<<dim3(DH_/BN, L_/BM, B_), 256>>>(p_G, p_em, nullptr, p_att,
        L_, DH_, L_, L_, DH_, DH_, (long)L_*L_, (long)L_*DH_, (long)L_*DH_, 0, 0);

    // 14. hidden = relu(att @ W_lin + b_lin)
    k_gemm_tc<0><<<dim3(H_/BN, N_/BM, 1), 256>>>(p_att, W_lin, b_lin, p_hid,
        N_, H_, DH_, DH_, H_, H_, 0, 0, 0, 1, 0);

    // 15. out = log_softmax(hidden @ W_fc + b_fc)
    k_fc<<<(N_*32 + 255)/256, 256>>>(W_fc, b_fc, out);
}